// round 15
// baseline (speedup 1.0000x reference)
#include <cuda_runtime.h>
#include <cuda_bf16.h>

#define T_STEPS   300
#define BATCH     2048
#define NPIX      225
#define NOUT      10
#define NTHREADS  288      // 2ch * 12 * 12 conv elements, pool-quad-major
#define SIGW      8        // 8*32 = 256 >= max classes
#define PTILE     28       // 28*10 = 280 <= 288: single-round linear

// ---------------- device scratch (no allocations allowed) ----------------
__device__ int   g_periods[BATCH * NPIX];
__device__ float g_lin[T_STEPS * BATCH * NOUT];   // 24.58 MB

// =========================================================================
// K1: per-pixel encoder first-spike step k (1-based), 0 if never spikes.
// v <- fma(0.1f, c - v, v); spike v>1; reset v - z*v -> exact +0 for z=1,
// so spikes are exactly {k, 2k, 3k, ...}.
// =========================================================================
__global__ void k_periods(const float* __restrict__ x) {
    int idx = blockIdx.x * blockDim.x + threadIdx.x;
    if (idx >= BATCH * NPIX) return;
    float c = __fmul_rn(x[idx], 10.0f);
    float v = 0.0f;
    int k = 0;
    for (int s = 1; s <= T_STEPS; ++s) {
        v = fmaf(0.1f, __fsub_rn(c, v), v);
        if (v > 1.0f) { k = s; break; }
    }
    g_periods[idx] = k;
}

// =========================================================================
// K2: one CTA per batch element. Produces g_lin[t][b][o].
// =========================================================================
struct __align__(16) Sm {
    float    wlin[NOUT * 72];          // 2880 B
    float    pooled[PTILE][76];        // 8512 B
    float    lin_pat[T_STEPS][NOUT];   // 12000 B
    unsigned sig[T_STEPS][SIGW];       // 9600 B
    unsigned hsh[T_STEPS];
    int      pid[T_STEPS];
    int      pat_of[T_STEPS];
    int      rep[T_STEPS];
    int      class_of[301];
    int      period_of[226];
    int      kk[NPIX];
    float    wconv[32];
    float    blin[NOUT];
    float    bconv[2];
    int      nclass, npat;
};  // ~41.5 KB

__global__ void __launch_bounds__(NTHREADS, 4)
k_forward(const float* __restrict__ conv_w, const float* __restrict__ conv_b,
          const float* __restrict__ lin_w,  const float* __restrict__ lin_b) {
    __shared__ Sm sm;
    const int tid = threadIdx.x;
    const int b   = blockIdx.x;

    // ---------------- phase 0: loads ----------------
    for (int i = tid; i < NOUT * 72; i += NTHREADS) sm.wlin[i] = lin_w[i];
    if (tid < 32)   sm.wconv[tid] = conv_w[tid];
    if (tid < NOUT) sm.blin[tid]  = lin_b[tid];
    if (tid < 2)    sm.bconv[tid] = conv_b[tid];
    if (tid < NPIX) sm.kk[tid]    = g_periods[b * NPIX + tid];
    for (int i = tid; i < 301; i += NTHREADS) sm.class_of[i] = 0;
    __syncthreads();

    // ---------------- phase 1: mark present periods ----------------
    if (tid < NPIX) {
        int k = sm.kk[tid];
        if (k > 0) sm.class_of[k] = 1;   // benign same-value race
    }
    __syncthreads();

    // ---------------- phase 2: build class list ----------------
    if (tid == 0) {
        int n = 0;
        for (int k = 1; k <= 300; ++k) {
            if (sm.class_of[k]) { sm.class_of[k] = n; sm.period_of[n] = k; n++; }
            else                  sm.class_of[k] = -1;
        }
        sm.nclass = n;
    }
    __syncthreads();
    const int nclass = sm.nclass;

    // ---------------- per-thread conv-tap geometry ----------------
    const int pb = tid >> 2, q = tid & 3;
    const int o  = pb / 36;
    const int rem = pb % 36;
    const int pi = rem / 6, pj = rem % 6;
    const int ci = 2 * pi + (q >> 1);
    const int cj = 2 * pj + (q & 1);
    const float bias_t = sm.bconv[o];
    float    wreg[16];
    unsigned mask[16];         // bit within sig word (0 => tap never active)
    unsigned wsel = 0;         // bit t4: word index LSB (for nclass<=64 path)
    unsigned woffpack[4] = {0, 0, 0, 0};   // per-tap word byte offsets (generic)
    #pragma unroll
    for (int kh = 0; kh < 4; ++kh)
        #pragma unroll
        for (int kw = 0; kw < 4; ++kw) {
            int t4 = kh * 4 + kw;
            int k  = sm.kk[(ci + kh) * 15 + (cj + kw)];
            int cls = (k > 0) ? sm.class_of[k] : -1;
            wreg[t4] = sm.wconv[o * 16 + t4];
            if (cls >= 0) {
                mask[t4] = 1u << (cls & 31);
                int wo = cls >> 5;
                wsel |= (unsigned)(wo & 1) << t4;
                woffpack[t4 >> 2] |= (unsigned)(wo << 2) << ((t4 & 3) << 3);
            } else {
                mask[t4] = 0u;
            }
        }

    // ---------------- phase 3: class-activity signatures (no atomics) ------
    for (int t = tid; t < T_STEPS; t += NTHREADS) {
        int tp1 = t + 1;
        #pragma unroll
        for (int w = 0; w < SIGW; ++w) {
            unsigned m = 0;
            int c0 = w * 32;
            int cn = nclass - c0; if (cn > 32) cn = 32;
            for (int j = 0; j < cn; ++j)
                if (tp1 % sm.period_of[c0 + j] == 0) m |= 1u << j;
            sm.sig[t][w] = m;
        }
    }
    __syncthreads();

    for (int t = tid; t < T_STEPS; t += NTHREADS) {
        unsigned h = 0;
        #pragma unroll
        for (int j = 0; j < SIGW; ++j)
            h = (h ^ sm.sig[t][j]) * 2654435761u;
        sm.hsh[t] = h;
    }
    __syncthreads();

    // ---------------- phase 4: dedup steps into patterns ----------------
    for (int t = tid; t < T_STEPS; t += NTHREADS) {
        unsigned h = sm.hsh[t];
        int f = t;
        for (int t2 = 0; t2 < t; ++t2) {
            if (sm.hsh[t2] == h) {
                bool eq = true;
                #pragma unroll
                for (int j = 0; j < SIGW; ++j)
                    eq = eq && (sm.sig[t2][j] == sm.sig[t][j]);
                if (eq) { f = t2; break; }
            }
        }
        sm.pid[t] = f;
    }
    __syncthreads();

    if (tid == 0) {
        int n = 0;
        for (int t = 0; t < T_STEPS; ++t) {
            int p = sm.pid[t];
            if (p == t) { sm.pat_of[t] = n; sm.rep[n] = t; n++; }
            else          sm.pat_of[t] = sm.pat_of[p];
        }
        sm.npat = n;
    }
    __syncthreads();
    const int npat = sm.npat;

    // ---------------- phase 5: per-pattern conv + pool + linear ----------------
    // conv numerics (frozen): taps ascending t4, predicated __fadd_rn chain
    // from 0; bias last. Two patterns in flight to hide FADD latency.
    for (int p0 = 0; p0 < npat; p0 += PTILE) {
        int ntile = npat - p0; if (ntile > PTILE) ntile = PTILE;

        if (nclass <= 32) {
            int pp = 0;
            for (; pp + 1 < ntile; pp += 2) {
                int tr0 = sm.rep[p0 + pp];
                int tr1 = sm.rep[p0 + pp + 1];
                unsigned s0 = sm.sig[tr0][0];
                unsigned s1 = sm.sig[tr1][0];
                float a0 = 0.0f, a1 = 0.0f;
                #pragma unroll
                for (int t4 = 0; t4 < 16; ++t4) {
                    if (s0 & mask[t4]) a0 = __fadd_rn(a0, wreg[t4]);
                    if (s1 & mask[t4]) a1 = __fadd_rn(a1, wreg[t4]);
                }
                a0 = __fadd_rn(a0, bias_t);
                a1 = __fadd_rn(a1, bias_t);
                float x0 = fmaxf(a0, __shfl_xor_sync(0xFFFFFFFFu, a0, 1));
                float x1 = fmaxf(a1, __shfl_xor_sync(0xFFFFFFFFu, a1, 1));
                float m0 = fmaxf(x0, __shfl_xor_sync(0xFFFFFFFFu, x0, 2));
                float m1 = fmaxf(x1, __shfl_xor_sync(0xFFFFFFFFu, x1, 2));
                if (q == 0) {
                    sm.pooled[pp][pb]     = m0;
                    sm.pooled[pp + 1][pb] = m1;
                }
            }
            if (pp < ntile) {
                int tr = sm.rep[p0 + pp];
                unsigned s0 = sm.sig[tr][0];
                float a = 0.0f;
                #pragma unroll
                for (int t4 = 0; t4 < 16; ++t4)
                    if (s0 & mask[t4]) a = __fadd_rn(a, wreg[t4]);
                a = __fadd_rn(a, bias_t);
                float x = fmaxf(a, __shfl_xor_sync(0xFFFFFFFFu, a, 1));
                float m = fmaxf(x, __shfl_xor_sync(0xFFFFFFFFu, x, 2));
                if (q == 0) sm.pooled[pp][pb] = m;
            }
        } else if (nclass <= 64) {
            int pp = 0;
            for (; pp + 1 < ntile; pp += 2) {
                int tr0 = sm.rep[p0 + pp];
                int tr1 = sm.rep[p0 + pp + 1];
                uint2 sa = *(const uint2*)&sm.sig[tr0][0];
                uint2 sb = *(const uint2*)&sm.sig[tr1][0];
                float a0 = 0.0f, a1 = 0.0f;
                #pragma unroll
                for (int t4 = 0; t4 < 16; ++t4) {
                    unsigned wa = ((wsel >> t4) & 1u) ? sa.y : sa.x;
                    unsigned wb = ((wsel >> t4) & 1u) ? sb.y : sb.x;
                    if (wa & mask[t4]) a0 = __fadd_rn(a0, wreg[t4]);
                    if (wb & mask[t4]) a1 = __fadd_rn(a1, wreg[t4]);
                }
                a0 = __fadd_rn(a0, bias_t);
                a1 = __fadd_rn(a1, bias_t);
                float x0 = fmaxf(a0, __shfl_xor_sync(0xFFFFFFFFu, a0, 1));
                float x1 = fmaxf(a1, __shfl_xor_sync(0xFFFFFFFFu, a1, 1));
                float m0 = fmaxf(x0, __shfl_xor_sync(0xFFFFFFFFu, x0, 2));
                float m1 = fmaxf(x1, __shfl_xor_sync(0xFFFFFFFFu, x1, 2));
                if (q == 0) {
                    sm.pooled[pp][pb]     = m0;
                    sm.pooled[pp + 1][pb] = m1;
                }
            }
            if (pp < ntile) {
                int tr = sm.rep[p0 + pp];
                uint2 sa = *(const uint2*)&sm.sig[tr][0];
                float a = 0.0f;
                #pragma unroll
                for (int t4 = 0; t4 < 16; ++t4) {
                    unsigned wa = ((wsel >> t4) & 1u) ? sa.y : sa.x;
                    if (wa & mask[t4]) a = __fadd_rn(a, wreg[t4]);
                }
                a = __fadd_rn(a, bias_t);
                float x = fmaxf(a, __shfl_xor_sync(0xFFFFFFFFu, a, 1));
                float m = fmaxf(x, __shfl_xor_sync(0xFFFFFFFFu, x, 2));
                if (q == 0) sm.pooled[pp][pb] = m;
            }
        } else {
            for (int pp = 0; pp < ntile; ++pp) {
                int tr = sm.rep[p0 + pp];
                const char* row = (const char*)&sm.sig[tr][0];
                float a = 0.0f;
                #pragma unroll
                for (int t4 = 0; t4 < 16; ++t4) {
                    unsigned off = (woffpack[t4 >> 2] >> ((t4 & 3) << 3)) & 0xFFu;
                    unsigned w = *(const unsigned*)(row + off);
                    if (w & mask[t4]) a = __fadd_rn(a, wreg[t4]);
                }
                a = __fadd_rn(a, bias_t);
                float x = fmaxf(a, __shfl_xor_sync(0xFFFFFFFFu, a, 1));
                float m = fmaxf(x, __shfl_xor_sync(0xFFFFFFFFu, x, 2));
                if (q == 0) sm.pooled[pp][pb] = m;
            }
        }
        __syncthreads();

        // Linear (frozen): cublas sliced1x4 tree — 4 mod-4 partials, 18 serial
        // FMAs each, halving combine (P0+P2)+(P1+P3), bias last.
        // 280 tasks <= 288 threads: single round.
        {
            int idx = tid;
            if (idx < ntile * NOUT) {
                int oo = idx % NOUT;
                int pp = idx / NOUT;
                const float* pv = sm.pooled[pp];
                const float* wv = &sm.wlin[oo * 72];
                float P0 = 0.0f, P1 = 0.0f, P2 = 0.0f, P3 = 0.0f;
                #pragma unroll
                for (int j = 0; j < 18; ++j) {
                    int k = j * 4;
                    P0 = fmaf(pv[k + 0], wv[k + 0], P0);
                    P1 = fmaf(pv[k + 1], wv[k + 1], P1);
                    P2 = fmaf(pv[k + 2], wv[k + 2], P2);
                    P3 = fmaf(pv[k + 3], wv[k + 3], P3);
                }
                float a02 = __fadd_rn(P0, P2);
                float a13 = __fadd_rn(P1, P3);
                float acc = __fadd_rn(a02, a13);
                sm.lin_pat[p0 + pp][oo] = __fadd_rn(acc, sm.blin[oo]);
            }
        }
        __syncthreads();
    }

    // ---------------- phase 6: expand lin_pat -> g_lin (parallel, coalesced)
    for (int idx = tid; idx < T_STEPS * NOUT; idx += NTHREADS) {
        int t = idx / NOUT;
        int o2 = idx - t * NOUT;
        g_lin[(long)t * (BATCH * NOUT) + b * NOUT + o2] =
            sm.lin_pat[sm.pat_of[t]][o2];
    }
}

// =========================================================================
// K3: decoder scan — one thread per (b, o). Math byte-identical to before.
// =========================================================================
__global__ void __launch_bounds__(256)
k_decode(float* __restrict__ out) {
    int gid = blockIdx.x * blockDim.x + threadIdx.x;
    if (gid >= BATCH * NOUT) return;
    float* __restrict__ mem = out + BATCH * NOUT;
    float* __restrict__ spk = mem + (long)T_STEPS * BATCH * NOUT;
    float v = 0.0f, cur = 0.0f, ss = 0.0f;
    const float* __restrict__ lp = g_lin + gid;
    for (int t = 0; t < T_STEPS; ++t) {
        float lv = lp[(long)t * (BATCH * NOUT)];
        float vd = fmaf(0.1f, __fsub_rn(cur, v), v);
        float id = fmaf(-0.2f, cur, cur);
        bool  sp = vd > 1.0f;
        v   = sp ? 0.0f : vd;
        cur = __fadd_rn(id, lv);
        float spf = sp ? 1.0f : 0.0f;
        ss += spf;
        long ofs = (long)t * (BATCH * NOUT) + gid;
        mem[ofs] = v;
        spk[ofs] = spf;
    }
    out[gid] = ss;
}

extern "C" void kernel_launch(void* const* d_in, const int* in_sizes, int n_in,
                              void* d_out, int out_size) {
    const float* x      = (const float*)d_in[0];
    const float* conv_w = (const float*)d_in[1];
    const float* conv_b = (const float*)d_in[2];
    const float* lin_w  = (const float*)d_in[3];
    const float* lin_b  = (const float*)d_in[4];
    float* out = (float*)d_out;

    k_periods<<<(BATCH * NPIX + 255) / 256, 256>>>(x);
    k_forward<<<BATCH, NTHREADS>>>(conv_w, conv_b, lin_w, lin_b);
    k_decode<<<(BATCH * NOUT + 255) / 256, 256>>>(out);
}

// round 16
// speedup vs baseline: 1.1005x; 1.1005x over previous
#include <cuda_runtime.h>
#include <cuda_bf16.h>

#define T_STEPS   300
#define BATCH     2048
#define NPIX      225
#define NOUT      10
#define NTHREADS  288      // 2ch * 12 * 12 conv elements, pool-quad-major
#define SIGW      8        // 8*32 = 256 >= max classes
#define PTILE     28       // 28*10 = 280 <= 288: single-round linear

// ---------------- device scratch (no allocations allowed) ----------------
__device__ int g_periods[BATCH * NPIX];

// =========================================================================
// K1: per-pixel encoder first-spike step k (1-based), 0 if never spikes.
// v <- fma(0.1f, c - v, v); spike v>1; reset v - z*v -> exact +0 for z=1,
// so spikes are exactly {k, 2k, 3k, ...}.
// Early exit: the fp32 recurrence preserves v <= c (exact-subtraction region
// + RN cannot cross the 0.9*(c-v) gap), so c <= 1 -> v > 1 never fires.
// =========================================================================
__global__ void k_periods(const float* __restrict__ x) {
    int idx = blockIdx.x * blockDim.x + threadIdx.x;
    if (idx >= BATCH * NPIX) return;
    float c = __fmul_rn(x[idx], 10.0f);
    int k = 0;
    if (c > 1.0f) {
        float v = 0.0f;
        for (int s = 1; s <= T_STEPS; ++s) {
            v = fmaf(0.1f, __fsub_rn(c, v), v);
            if (v > 1.0f) { k = s; break; }
        }
    }
    g_periods[idx] = k;
}

// =========================================================================
// K2: one CTA per batch element.
// =========================================================================
struct __align__(16) Sm {
    float    wlin[NOUT * 72];          // 2880 B
    float    pooled[PTILE][76];        // 8512 B
    float    lin_pat[T_STEPS][NOUT];   // 12000 B
    unsigned sig[T_STEPS][SIGW];       // 9600 B
    unsigned hsh[T_STEPS];
    int      pid[T_STEPS];
    int      pat_of[T_STEPS];
    int      rep[T_STEPS];
    int      class_of[301];
    int      period_of[226];
    int      kk[NPIX];
    float    wconv[32];
    float    blin[NOUT];
    float    bconv[2];
    int      nclass, npat;
};  // ~41.5 KB

__global__ void __launch_bounds__(NTHREADS, 4)
k_forward(const float* __restrict__ conv_w, const float* __restrict__ conv_b,
          const float* __restrict__ lin_w,  const float* __restrict__ lin_b,
          float* __restrict__ out) {
    __shared__ Sm sm;
    const int tid = threadIdx.x;
    const int b   = blockIdx.x;

    // ---------------- phase 0: loads ----------------
    for (int i = tid; i < NOUT * 72; i += NTHREADS) sm.wlin[i] = lin_w[i];
    if (tid < 32)   sm.wconv[tid] = conv_w[tid];
    if (tid < NOUT) sm.blin[tid]  = lin_b[tid];
    if (tid < 2)    sm.bconv[tid] = conv_b[tid];
    if (tid < NPIX) sm.kk[tid]    = g_periods[b * NPIX + tid];
    for (int i = tid; i < 301; i += NTHREADS) sm.class_of[i] = 0;
    __syncthreads();

    // ---------------- phase 1: mark present periods ----------------
    if (tid < NPIX) {
        int k = sm.kk[tid];
        if (k > 0) sm.class_of[k] = 1;   // benign same-value race
    }
    __syncthreads();

    // ---------------- phase 2: build class list ----------------
    if (tid == 0) {
        int n = 0;
        for (int k = 1; k <= 300; ++k) {
            if (sm.class_of[k]) { sm.class_of[k] = n; sm.period_of[n] = k; n++; }
            else                  sm.class_of[k] = -1;
        }
        sm.nclass = n;
    }
    __syncthreads();
    const int nclass = sm.nclass;

    // ---------------- per-thread conv-tap geometry ----------------
    const int pb = tid >> 2, q = tid & 3;
    const int o  = pb / 36;
    const int rem = pb % 36;
    const int pi = rem / 6, pj = rem % 6;
    const int ci = 2 * pi + (q >> 1);
    const int cj = 2 * pj + (q & 1);
    const float bias_t = sm.bconv[o];
    float    wreg[16];
    unsigned mask[16];         // bit within sig word (0 => tap never active)
    unsigned wsel = 0;         // bit t4: word index LSB (for nclass<=64 path)
    unsigned woffpack[4] = {0, 0, 0, 0};   // per-tap word byte offsets (generic)
    #pragma unroll
    for (int kh = 0; kh < 4; ++kh)
        #pragma unroll
        for (int kw = 0; kw < 4; ++kw) {
            int t4 = kh * 4 + kw;
            int k  = sm.kk[(ci + kh) * 15 + (cj + kw)];
            int cls = (k > 0) ? sm.class_of[k] : -1;
            wreg[t4] = sm.wconv[o * 16 + t4];
            if (cls >= 0) {
                mask[t4] = 1u << (cls & 31);
                int wo = cls >> 5;
                wsel |= (unsigned)(wo & 1) << t4;
                woffpack[t4 >> 2] |= (unsigned)(wo << 2) << ((t4 & 3) << 3);
            } else {
                mask[t4] = 0u;
            }
        }

    // ---------------- phase 3: class-activity signatures (no atomics) ------
    for (int t = tid; t < T_STEPS; t += NTHREADS) {
        int tp1 = t + 1;
        #pragma unroll
        for (int w = 0; w < SIGW; ++w) {
            unsigned m = 0;
            int c0 = w * 32;
            int cn = nclass - c0; if (cn > 32) cn = 32;
            for (int j = 0; j < cn; ++j)
                if (tp1 % sm.period_of[c0 + j] == 0) m |= 1u << j;
            sm.sig[t][w] = m;
        }
    }
    __syncthreads();

    for (int t = tid; t < T_STEPS; t += NTHREADS) {
        unsigned h = 0;
        #pragma unroll
        for (int j = 0; j < SIGW; ++j)
            h = (h ^ sm.sig[t][j]) * 2654435761u;
        sm.hsh[t] = h;
    }
    __syncthreads();

    // ---------------- phase 4: dedup steps into patterns ----------------
    for (int t = tid; t < T_STEPS; t += NTHREADS) {
        unsigned h = sm.hsh[t];
        int f = t;
        for (int t2 = 0; t2 < t; ++t2) {
            if (sm.hsh[t2] == h) {
                bool eq = true;
                #pragma unroll
                for (int j = 0; j < SIGW; ++j)
                    eq = eq && (sm.sig[t2][j] == sm.sig[t][j]);
                if (eq) { f = t2; break; }
            }
        }
        sm.pid[t] = f;
    }
    __syncthreads();

    if (tid == 0) {
        int n = 0;
        for (int t = 0; t < T_STEPS; ++t) {
            int p = sm.pid[t];
            if (p == t) { sm.pat_of[t] = n; sm.rep[n] = t; n++; }
            else          sm.pat_of[t] = sm.pat_of[p];
        }
        sm.npat = n;
    }
    __syncthreads();
    const int npat = sm.npat;

    // ---------------- phase 5: per-pattern conv + pool + linear ----------------
    // conv numerics (frozen): taps ascending t4, predicated __fadd_rn chain
    // from 0; bias last. Two patterns in flight to hide FADD latency.
    for (int p0 = 0; p0 < npat; p0 += PTILE) {
        int ntile = npat - p0; if (ntile > PTILE) ntile = PTILE;

        if (nclass <= 32) {
            int pp = 0;
            for (; pp + 1 < ntile; pp += 2) {
                int tr0 = sm.rep[p0 + pp];
                int tr1 = sm.rep[p0 + pp + 1];
                unsigned s0 = sm.sig[tr0][0];
                unsigned s1 = sm.sig[tr1][0];
                float a0 = 0.0f, a1 = 0.0f;
                #pragma unroll
                for (int t4 = 0; t4 < 16; ++t4) {
                    if (s0 & mask[t4]) a0 = __fadd_rn(a0, wreg[t4]);
                    if (s1 & mask[t4]) a1 = __fadd_rn(a1, wreg[t4]);
                }
                a0 = __fadd_rn(a0, bias_t);
                a1 = __fadd_rn(a1, bias_t);
                float x0 = fmaxf(a0, __shfl_xor_sync(0xFFFFFFFFu, a0, 1));
                float x1 = fmaxf(a1, __shfl_xor_sync(0xFFFFFFFFu, a1, 1));
                float m0 = fmaxf(x0, __shfl_xor_sync(0xFFFFFFFFu, x0, 2));
                float m1 = fmaxf(x1, __shfl_xor_sync(0xFFFFFFFFu, x1, 2));
                if (q == 0) {
                    sm.pooled[pp][pb]     = m0;
                    sm.pooled[pp + 1][pb] = m1;
                }
            }
            if (pp < ntile) {
                int tr = sm.rep[p0 + pp];
                unsigned s0 = sm.sig[tr][0];
                float a = 0.0f;
                #pragma unroll
                for (int t4 = 0; t4 < 16; ++t4)
                    if (s0 & mask[t4]) a = __fadd_rn(a, wreg[t4]);
                a = __fadd_rn(a, bias_t);
                float x = fmaxf(a, __shfl_xor_sync(0xFFFFFFFFu, a, 1));
                float m = fmaxf(x, __shfl_xor_sync(0xFFFFFFFFu, x, 2));
                if (q == 0) sm.pooled[pp][pb] = m;
            }
        } else if (nclass <= 64) {
            int pp = 0;
            for (; pp + 1 < ntile; pp += 2) {
                int tr0 = sm.rep[p0 + pp];
                int tr1 = sm.rep[p0 + pp + 1];
                uint2 sa = *(const uint2*)&sm.sig[tr0][0];
                uint2 sb = *(const uint2*)&sm.sig[tr1][0];
                float a0 = 0.0f, a1 = 0.0f;
                #pragma unroll
                for (int t4 = 0; t4 < 16; ++t4) {
                    unsigned wa = ((wsel >> t4) & 1u) ? sa.y : sa.x;
                    unsigned wb = ((wsel >> t4) & 1u) ? sb.y : sb.x;
                    if (wa & mask[t4]) a0 = __fadd_rn(a0, wreg[t4]);
                    if (wb & mask[t4]) a1 = __fadd_rn(a1, wreg[t4]);
                }
                a0 = __fadd_rn(a0, bias_t);
                a1 = __fadd_rn(a1, bias_t);
                float x0 = fmaxf(a0, __shfl_xor_sync(0xFFFFFFFFu, a0, 1));
                float x1 = fmaxf(a1, __shfl_xor_sync(0xFFFFFFFFu, a1, 1));
                float m0 = fmaxf(x0, __shfl_xor_sync(0xFFFFFFFFu, x0, 2));
                float m1 = fmaxf(x1, __shfl_xor_sync(0xFFFFFFFFu, x1, 2));
                if (q == 0) {
                    sm.pooled[pp][pb]     = m0;
                    sm.pooled[pp + 1][pb] = m1;
                }
            }
            if (pp < ntile) {
                int tr = sm.rep[p0 + pp];
                uint2 sa = *(const uint2*)&sm.sig[tr][0];
                float a = 0.0f;
                #pragma unroll
                for (int t4 = 0; t4 < 16; ++t4) {
                    unsigned wa = ((wsel >> t4) & 1u) ? sa.y : sa.x;
                    if (wa & mask[t4]) a = __fadd_rn(a, wreg[t4]);
                }
                a = __fadd_rn(a, bias_t);
                float x = fmaxf(a, __shfl_xor_sync(0xFFFFFFFFu, a, 1));
                float m = fmaxf(x, __shfl_xor_sync(0xFFFFFFFFu, x, 2));
                if (q == 0) sm.pooled[pp][pb] = m;
            }
        } else {
            for (int pp = 0; pp < ntile; ++pp) {
                int tr = sm.rep[p0 + pp];
                const char* row = (const char*)&sm.sig[tr][0];
                float a = 0.0f;
                #pragma unroll
                for (int t4 = 0; t4 < 16; ++t4) {
                    unsigned off = (woffpack[t4 >> 2] >> ((t4 & 3) << 3)) & 0xFFu;
                    unsigned w = *(const unsigned*)(row + off);
                    if (w & mask[t4]) a = __fadd_rn(a, wreg[t4]);
                }
                a = __fadd_rn(a, bias_t);
                float x = fmaxf(a, __shfl_xor_sync(0xFFFFFFFFu, a, 1));
                float m = fmaxf(x, __shfl_xor_sync(0xFFFFFFFFu, x, 2));
                if (q == 0) sm.pooled[pp][pb] = m;
            }
        }
        __syncthreads();

        // Linear (frozen): cublas sliced1x4 tree — 4 mod-4 partials, 18 serial
        // FMAs each, halving combine (P0+P2)+(P1+P3), bias last.
        // 280 tasks <= 288 threads: single round.
        if (tid < ntile * NOUT) {
            int oo = tid % NOUT;
            int pp = tid / NOUT;
            const float* pv = sm.pooled[pp];
            const float* wv = &sm.wlin[oo * 72];
            float P0 = 0.0f, P1 = 0.0f, P2 = 0.0f, P3 = 0.0f;
            #pragma unroll
            for (int j = 0; j < 18; ++j) {
                int k = j * 4;
                P0 = fmaf(pv[k + 0], wv[k + 0], P0);
                P1 = fmaf(pv[k + 1], wv[k + 1], P1);
                P2 = fmaf(pv[k + 2], wv[k + 2], P2);
                P3 = fmaf(pv[k + 3], wv[k + 3], P3);
            }
            float a02 = __fadd_rn(P0, P2);
            float a13 = __fadd_rn(P1, P3);
            float acc = __fadd_rn(a02, a13);
            sm.lin_pat[p0 + pp][oo] = __fadd_rn(acc, sm.blin[oo]);
        }
        __syncthreads();
    }

    // ---------------- phase 6: fused sequential decoder (frozen) -----------
    if (tid < NOUT) {
        float v = 0.0f, cur = 0.0f, ss = 0.0f;
        float* __restrict__ mem = out + BATCH * NOUT;
        float* __restrict__ spk = mem + (long)T_STEPS * BATCH * NOUT;
        const int base = b * NOUT + tid;
        for (int t = 0; t < T_STEPS; ++t) {
            float lv = sm.lin_pat[sm.pat_of[t]][tid];
            float vd = fmaf(0.1f, __fsub_rn(cur, v), v);
            float id = fmaf(-0.2f, cur, cur);
            bool  sp = vd > 1.0f;
            v   = sp ? 0.0f : vd;
            cur = __fadd_rn(id, lv);
            float spf = sp ? 1.0f : 0.0f;
            ss += spf;
            long ofs = (long)t * (BATCH * NOUT) + base;
            mem[ofs] = v;
            spk[ofs] = spf;
        }
        out[base] = ss;
    }
}

extern "C" void kernel_launch(void* const* d_in, const int* in_sizes, int n_in,
                              void* d_out, int out_size) {
    const float* x      = (const float*)d_in[0];
    const float* conv_w = (const float*)d_in[1];
    const float* conv_b = (const float*)d_in[2];
    const float* lin_w  = (const float*)d_in[3];
    const float* lin_b  = (const float*)d_in[4];
    float* out = (float*)d_out;

    k_periods<<<(BATCH * NPIX + 255) / 256, 256>>>(x);
    k_forward<<<BATCH, NTHREADS>>>(conv_w, conv_b, lin_w, lin_b, out);
}

// round 17
// speedup vs baseline: 1.1425x; 1.0382x over previous
#include <cuda_runtime.h>
#include <cuda_bf16.h>

#define T_STEPS   300
#define BATCH     2048
#define NPIX      225
#define NOUT      10
#define NTHREADS  288      // 2ch * 12 * 12 conv elements, pool-quad-major
#define SIGW      8        // 8*32 = 256 >= max classes
#define PTILE     28       // 28*10 = 280 <= 288: single-round linear

// ---------------- device scratch (no allocations allowed) ----------------
__device__ int g_periods[BATCH * NPIX];

// =========================================================================
// K1: per-pixel encoder first-spike step k (1-based), 0 if never spikes.
// v <- fma(0.1f, c - v, v); spike v>1; reset v - z*v -> exact +0 for z=1,
// so spikes are exactly {k, 2k, 3k, ...}. Early exit: recurrence preserves
// v <= c, so c <= 1 can never fire.
// =========================================================================
__global__ void k_periods(const float* __restrict__ x) {
    int idx = blockIdx.x * blockDim.x + threadIdx.x;
    if (idx >= BATCH * NPIX) return;
    float c = __fmul_rn(x[idx], 10.0f);
    int k = 0;
    if (c > 1.0f) {
        float v = 0.0f;
        for (int s = 1; s <= T_STEPS; ++s) {
            v = fmaf(0.1f, __fsub_rn(c, v), v);
            if (v > 1.0f) { k = s; break; }
        }
    }
    g_periods[idx] = k;
}

// 8 taps, two patterns interleaved. Per tap per pattern:
// LOP3(and)->predicate fused + predicated add.rn.f32. Chain order per
// accumulator is ascending taps — byte-identical numerics to the
// reference-matched predicated-FADD chain.
#define CONV_TAPS8_PAIR(A0, A1, S0, S1, MM, WW, B)                          \
    asm volatile("{\n\t"                                                     \
        ".reg .pred p0, p1, qq;\n\t"                                         \
        ".reg .b32 t0, t1;\n\t"                                              \
        "setp.ne.u32 qq, 0, 0;\n\t"                                          \
        "lop3.or.b32 t0|p0, %2, %4, 0, 0xC0, qq;\n\t"                        \
        "lop3.or.b32 t1|p1, %3, %4, 0, 0xC0, qq;\n\t"                        \
        "@p0 add.rn.f32 %0, %0, %12;\n\t"                                    \
        "@p1 add.rn.f32 %1, %1, %12;\n\t"                                    \
        "lop3.or.b32 t0|p0, %2, %5, 0, 0xC0, qq;\n\t"                        \
        "lop3.or.b32 t1|p1, %3, %5, 0, 0xC0, qq;\n\t"                        \
        "@p0 add.rn.f32 %0, %0, %13;\n\t"                                    \
        "@p1 add.rn.f32 %1, %1, %13;\n\t"                                    \
        "lop3.or.b32 t0|p0, %2, %6, 0, 0xC0, qq;\n\t"                        \
        "lop3.or.b32 t1|p1, %3, %6, 0, 0xC0, qq;\n\t"                        \
        "@p0 add.rn.f32 %0, %0, %14;\n\t"                                    \
        "@p1 add.rn.f32 %1, %1, %14;\n\t"                                    \
        "lop3.or.b32 t0|p0, %2, %7, 0, 0xC0, qq;\n\t"                        \
        "lop3.or.b32 t1|p1, %3, %7, 0, 0xC0, qq;\n\t"                        \
        "@p0 add.rn.f32 %0, %0, %15;\n\t"                                    \
        "@p1 add.rn.f32 %1, %1, %15;\n\t"                                    \
        "lop3.or.b32 t0|p0, %2, %8, 0, 0xC0, qq;\n\t"                        \
        "lop3.or.b32 t1|p1, %3, %8, 0, 0xC0, qq;\n\t"                        \
        "@p0 add.rn.f32 %0, %0, %16;\n\t"                                    \
        "@p1 add.rn.f32 %1, %1, %16;\n\t"                                    \
        "lop3.or.b32 t0|p0, %2, %9, 0, 0xC0, qq;\n\t"                        \
        "lop3.or.b32 t1|p1, %3, %9, 0, 0xC0, qq;\n\t"                        \
        "@p0 add.rn.f32 %0, %0, %17;\n\t"                                    \
        "@p1 add.rn.f32 %1, %1, %17;\n\t"                                    \
        "lop3.or.b32 t0|p0, %2, %10, 0, 0xC0, qq;\n\t"                       \
        "lop3.or.b32 t1|p1, %3, %10, 0, 0xC0, qq;\n\t"                       \
        "@p0 add.rn.f32 %0, %0, %18;\n\t"                                    \
        "@p1 add.rn.f32 %1, %1, %18;\n\t"                                    \
        "lop3.or.b32 t0|p0, %2, %11, 0, 0xC0, qq;\n\t"                       \
        "lop3.or.b32 t1|p1, %3, %11, 0, 0xC0, qq;\n\t"                       \
        "@p0 add.rn.f32 %0, %0, %19;\n\t"                                    \
        "@p1 add.rn.f32 %1, %1, %19;\n\t"                                    \
        "}"                                                                  \
        : "+f"(A0), "+f"(A1)                                                 \
        : "r"(S0), "r"(S1),                                                  \
          "r"((MM)[(B)+0]), "r"((MM)[(B)+1]), "r"((MM)[(B)+2]),              \
          "r"((MM)[(B)+3]), "r"((MM)[(B)+4]), "r"((MM)[(B)+5]),              \
          "r"((MM)[(B)+6]), "r"((MM)[(B)+7]),                                \
          "f"((WW)[(B)+0]), "f"((WW)[(B)+1]), "f"((WW)[(B)+2]),              \
          "f"((WW)[(B)+3]), "f"((WW)[(B)+4]), "f"((WW)[(B)+5]),              \
          "f"((WW)[(B)+6]), "f"((WW)[(B)+7]))

// =========================================================================
// K2: one CTA per batch element.
// =========================================================================
struct __align__(16) Sm {
    float    wlin[NOUT * 72];          // 2880 B
    float    pooled[PTILE][76];        // 8512 B
    float    lin_pat[T_STEPS][NOUT];   // 12000 B
    unsigned sig[T_STEPS][SIGW];       // 9600 B
    unsigned hsh[T_STEPS];
    int      pid[T_STEPS];
    int      pat_of[T_STEPS];
    int      rep[T_STEPS];
    int      class_of[301];
    int      period_of[226];
    int      kk[NPIX];
    float    wconv[32];
    float    blin[NOUT];
    float    bconv[2];
    int      nclass, npat;
};  // ~41.5 KB

__global__ void __launch_bounds__(NTHREADS, 4)
k_forward(const float* __restrict__ conv_w, const float* __restrict__ conv_b,
          const float* __restrict__ lin_w,  const float* __restrict__ lin_b,
          float* __restrict__ out) {
    __shared__ Sm sm;
    const int tid = threadIdx.x;
    const int b   = blockIdx.x;

    // ---------------- phase 0: loads ----------------
    for (int i = tid; i < NOUT * 72; i += NTHREADS) sm.wlin[i] = lin_w[i];
    if (tid < 32)   sm.wconv[tid] = conv_w[tid];
    if (tid < NOUT) sm.blin[tid]  = lin_b[tid];
    if (tid < 2)    sm.bconv[tid] = conv_b[tid];
    if (tid < NPIX) sm.kk[tid]    = g_periods[b * NPIX + tid];
    for (int i = tid; i < 301; i += NTHREADS) sm.class_of[i] = 0;
    __syncthreads();

    // ---------------- phase 1: mark present periods ----------------
    if (tid < NPIX) {
        int k = sm.kk[tid];
        if (k > 0) sm.class_of[k] = 1;   // benign same-value race
    }
    __syncthreads();

    // ---------------- phase 2: build class list ----------------
    if (tid == 0) {
        int n = 0;
        for (int k = 1; k <= 300; ++k) {
            if (sm.class_of[k]) { sm.class_of[k] = n; sm.period_of[n] = k; n++; }
            else                  sm.class_of[k] = -1;
        }
        sm.nclass = n;
    }
    __syncthreads();
    const int nclass = sm.nclass;

    // ---------------- per-thread conv-tap geometry ----------------
    const int pb = tid >> 2, q = tid & 3;
    const int o  = pb / 36;
    const int rem = pb % 36;
    const int pi = rem / 6, pj = rem % 6;
    const int ci = 2 * pi + (q >> 1);
    const int cj = 2 * pj + (q & 1);
    const float bias_t = sm.bconv[o];
    float    wreg[16];
    unsigned mask[16];         // bit within its word (0 => tap never active)
    unsigned woffpack[4] = {0, 0, 0, 0};   // per-tap word byte offsets (generic)
    int      hi_class = 0;     // any tap class >= 32?
    #pragma unroll
    for (int kh = 0; kh < 4; ++kh)
        #pragma unroll
        for (int kw = 0; kw < 4; ++kw) {
            int t4 = kh * 4 + kw;
            int k  = sm.kk[(ci + kh) * 15 + (cj + kw)];
            int cls = (k > 0) ? sm.class_of[k] : -1;
            wreg[t4] = sm.wconv[o * 16 + t4];
            if (cls >= 0) {
                mask[t4] = 1u << (cls & 31);
                int wo = cls >> 5;
                woffpack[t4 >> 2] |= (unsigned)(wo << 2) << ((t4 & 3) << 3);
                hi_class |= (cls >= 32);
            } else {
                mask[t4] = 0u;
            }
        }
    // warp-uniform fast-path vote: all taps of all lanes in word 0
    const bool fastw = !__any_sync(0xFFFFFFFFu, hi_class);

    // ---------------- phase 3: class-activity signatures (no atomics) ------
    for (int t = tid; t < T_STEPS; t += NTHREADS) {
        int tp1 = t + 1;
        #pragma unroll
        for (int w = 0; w < SIGW; ++w) {
            unsigned m = 0;
            int c0 = w * 32;
            int cn = nclass - c0; if (cn > 32) cn = 32;
            for (int j = 0; j < cn; ++j)
                if (tp1 % sm.period_of[c0 + j] == 0) m |= 1u << j;
            sm.sig[t][w] = m;
        }
    }
    __syncthreads();

    for (int t = tid; t < T_STEPS; t += NTHREADS) {
        unsigned h = 0;
        #pragma unroll
        for (int j = 0; j < SIGW; ++j)
            h = (h ^ sm.sig[t][j]) * 2654435761u;
        sm.hsh[t] = h;
    }
    __syncthreads();

    // ---------------- phase 4: dedup steps into patterns ----------------
    for (int t = tid; t < T_STEPS; t += NTHREADS) {
        unsigned h = sm.hsh[t];
        int f = t;
        for (int t2 = 0; t2 < t; ++t2) {
            if (sm.hsh[t2] == h) {
                bool eq = true;
                #pragma unroll
                for (int j = 0; j < SIGW; ++j)
                    eq = eq && (sm.sig[t2][j] == sm.sig[t][j]);
                if (eq) { f = t2; break; }
            }
        }
        sm.pid[t] = f;
    }
    __syncthreads();

    if (tid == 0) {
        int n = 0;
        for (int t = 0; t < T_STEPS; ++t) {
            int p = sm.pid[t];
            if (p == t) { sm.pat_of[t] = n; sm.rep[n] = t; n++; }
            else          sm.pat_of[t] = sm.pat_of[p];
        }
        sm.npat = n;
    }
    __syncthreads();
    const int npat = sm.npat;

    // ---------------- phase 5: per-pattern conv + pool + linear ----------------
    // conv numerics (frozen): taps ascending t4, predicated add.rn.f32 chain
    // from 0; bias last. Two patterns in flight to hide FADD latency.
    for (int p0 = 0; p0 < npat; p0 += PTILE) {
        int ntile = npat - p0; if (ntile > PTILE) ntile = PTILE;

        if (fastw) {
            // all tap classes < 32 for this warp: word0-only, fused LOP3|p taps
            int pp = 0;
            for (; pp + 1 < ntile; pp += 2) {
                unsigned s0 = sm.sig[sm.rep[p0 + pp]][0];
                unsigned s1 = sm.sig[sm.rep[p0 + pp + 1]][0];
                float a0 = 0.0f, a1 = 0.0f;
                CONV_TAPS8_PAIR(a0, a1, s0, s1, mask, wreg, 0);
                CONV_TAPS8_PAIR(a0, a1, s0, s1, mask, wreg, 8);
                a0 = __fadd_rn(a0, bias_t);
                a1 = __fadd_rn(a1, bias_t);
                float x0 = fmaxf(a0, __shfl_xor_sync(0xFFFFFFFFu, a0, 1));
                float x1 = fmaxf(a1, __shfl_xor_sync(0xFFFFFFFFu, a1, 1));
                float m0 = fmaxf(x0, __shfl_xor_sync(0xFFFFFFFFu, x0, 2));
                float m1 = fmaxf(x1, __shfl_xor_sync(0xFFFFFFFFu, x1, 2));
                if (q == 0) {
                    sm.pooled[pp][pb]     = m0;
                    sm.pooled[pp + 1][pb] = m1;
                }
            }
            if (pp < ntile) {
                unsigned s0 = sm.sig[sm.rep[p0 + pp]][0];
                float a = 0.0f, adump = 0.0f;
                CONV_TAPS8_PAIR(a, adump, s0, s0, mask, wreg, 0);
                CONV_TAPS8_PAIR(a, adump, s0, s0, mask, wreg, 8);
                a = __fadd_rn(a, bias_t);
                float x = fmaxf(a, __shfl_xor_sync(0xFFFFFFFFu, a, 1));
                float m = fmaxf(x, __shfl_xor_sync(0xFFFFFFFFu, x, 2));
                if (q == 0) sm.pooled[pp][pb] = m;
            }
        } else {
            // generic: per-tap word via packed byte offsets (rare warps)
            for (int pp = 0; pp < ntile; ++pp) {
                int tr = sm.rep[p0 + pp];
                const char* row = (const char*)&sm.sig[tr][0];
                float a = 0.0f;
                #pragma unroll
                for (int t4 = 0; t4 < 16; ++t4) {
                    unsigned off = (woffpack[t4 >> 2] >> ((t4 & 3) << 3)) & 0xFFu;
                    unsigned w = *(const unsigned*)(row + off);
                    if (w & mask[t4]) a = __fadd_rn(a, wreg[t4]);
                }
                a = __fadd_rn(a, bias_t);
                float x = fmaxf(a, __shfl_xor_sync(0xFFFFFFFFu, a, 1));
                float m = fmaxf(x, __shfl_xor_sync(0xFFFFFFFFu, x, 2));
                if (q == 0) sm.pooled[pp][pb] = m;
            }
        }
        __syncthreads();

        // Linear (frozen): cublas sliced1x4 tree — 4 mod-4 partials, 18 serial
        // FMAs each, halving combine (P0+P2)+(P1+P3), bias last. Single round.
        if (tid < ntile * NOUT) {
            int oo = tid % NOUT;
            int pp = tid / NOUT;
            const float* pv = sm.pooled[pp];
            const float* wv = &sm.wlin[oo * 72];
            float P0 = 0.0f, P1 = 0.0f, P2 = 0.0f, P3 = 0.0f;
            #pragma unroll
            for (int j = 0; j < 18; ++j) {
                int k = j * 4;
                P0 = fmaf(pv[k + 0], wv[k + 0], P0);
                P1 = fmaf(pv[k + 1], wv[k + 1], P1);
                P2 = fmaf(pv[k + 2], wv[k + 2], P2);
                P3 = fmaf(pv[k + 3], wv[k + 3], P3);
            }
            float a02 = __fadd_rn(P0, P2);
            float a13 = __fadd_rn(P1, P3);
            float acc = __fadd_rn(a02, a13);
            sm.lin_pat[p0 + pp][oo] = __fadd_rn(acc, sm.blin[oo]);
        }
        __syncthreads();
    }

    // ---------------- phase 6: fused sequential decoder (frozen) -----------
    if (tid < NOUT) {
        float v = 0.0f, cur = 0.0f, ss = 0.0f;
        float* __restrict__ mem = out + BATCH * NOUT;
        float* __restrict__ spk = mem + (long)T_STEPS * BATCH * NOUT;
        const int base = b * NOUT + tid;
        for (int t = 0; t < T_STEPS; ++t) {
            float lv = sm.lin_pat[sm.pat_of[t]][tid];
            float vd = fmaf(0.1f, __fsub_rn(cur, v), v);
            float id = fmaf(-0.2f, cur, cur);
            bool  sp = vd > 1.0f;
            v   = sp ? 0.0f : vd;
            cur = __fadd_rn(id, lv);
            float spf = sp ? 1.0f : 0.0f;
            ss += spf;
            long ofs = (long)t * (BATCH * NOUT) + base;
            mem[ofs] = v;
            spk[ofs] = spf;
        }
        out[base] = ss;
    }
}

extern "C" void kernel_launch(void* const* d_in, const int* in_sizes, int n_in,
                              void* d_out, int out_size) {
    const float* x      = (const float*)d_in[0];
    const float* conv_w = (const float*)d_in[1];
    const float* conv_b = (const float*)d_in[2];
    const float* lin_w  = (const float*)d_in[3];
    const float* lin_b  = (const float*)d_in[4];
    float* out = (float*)d_out;

    k_periods<<<(BATCH * NPIX + 255) / 256, 256>>>(x);
    k_forward<<<BATCH, NTHREADS>>>(conv_w, conv_b, lin_w, lin_b, out);
}